// round 12
// baseline (speedup 1.0000x reference)
#include <cuda_runtime.h>
#include <float.h>

// Problem constants (fixed: B=4, M=1024, N=32768)
#define BB 4
#define MM 1024
#define NN 32768
#define NPAIRS (NN / 2)        // 16384 point-pairs per batch
#define NCHUNK 184             // 184*4 = 736 blocks < 740 = 148 SM * 5 -> 1 wave at occ5
#define TILE 90                // ceil(16384/184); tail clamped at copy time
#define KT 8                   // keypoints per thread
#define NTHREADS 128           // 128 * 8 = 1024 = all keypoints per block
#define NROWS (BB * MM)        // 4096
#define FBLOCKS 64             // final blocks: 64 rows x 4 chunk-quarters each
#define CQ 4
#define CPQ (NCHUNK / CQ)      // 46 chunks per quarter

typedef unsigned long long u64;

// Scratch (no cudaMalloc allowed). Chunk-major: [chunk][b*MM+m]
__device__ float g_partial[NCHUNK * NROWS];
__device__ float g_bsum[FBLOCKS];
__device__ unsigned g_done;   // zero-init at load; last block resets -> replay-safe

// ---- packed f32x2 helpers (Blackwell FFMA2 path) ----
__device__ __forceinline__ u64 fma2(u64 a, u64 b, u64 c) {
    u64 d; asm("fma.rn.f32x2 %0, %1, %2, %3;" : "=l"(d) : "l"(a), "l"(b), "l"(c));
    return d;
}
__device__ __forceinline__ u64 mul2(u64 a, u64 b) {
    u64 d; asm("mul.rn.f32x2 %0, %1, %2;" : "=l"(d) : "l"(a), "l"(b));
    return d;
}
__device__ __forceinline__ u64 dup2(float x) {
    u64 d; asm("mov.b64 %0, {%1, %1};" : "=l"(d) : "f"(x));
    return d;
}
__device__ __forceinline__ void unpack2(u64 v, float& lo, float& hi) {
    asm("mov.b64 {%0, %1}, %2;" : "=f"(lo), "=f"(hi) : "l"(v));
}

// --- Kernel 1: per (chunk, b) block: min over chunk's points for all 1024 keypoints.
// v = |p|^2 - 2 k.p  (d2 = |k|^2 + min v applied in the final kernel).
__global__ void __launch_bounds__(NTHREADS, 5)
min_kernel(const float* __restrict__ kpt, const float* __restrict__ pc) {
    const int chunk = blockIdx.x;
    const int b     = blockIdx.y;
    const int t     = threadIdx.x;
    const int m0    = t * KT;

    // smem: per pair i: s_pts[2i]={x2,y2}, s_pts[2i+1]={z2,pp}  (two LDS.128 per iter)
    __shared__ ulonglong2 s_pts[2 * TILE];

    // Copy phase: stage this chunk's point-pairs + packed |p|^2 (computed once).
    if (t < TILE) {
        int q = min(chunk * TILE + t, NPAIRS - 1);  // tail clamp: dup pair is a min no-op
        const float* pcb = pc + (size_t)b * 3 * NN;
        u64 x2 = ((const u64*)pcb)[q];
        u64 y2 = ((const u64*)(pcb + NN))[q];
        u64 z2 = ((const u64*)(pcb + 2 * NN))[q];
        u64 pp = fma2(z2, z2, fma2(y2, y2, mul2(x2, x2)));  // (|p0|^2, |p1|^2)
        ulonglong2 a, c;
        a.x = x2; a.y = y2;
        c.x = z2; c.y = pp;
        s_pts[2 * t]     = a;
        s_pts[2 * t + 1] = c;
    }

    // Per-thread keypoints, scaled by -2, duplicated into both f32x2 halves (hoisted).
    const float* kb = kpt + (size_t)b * 3 * MM;
    u64 knx[KT], kny[KT], knz[KT];
    float mnl[KT], mnh[KT];
#pragma unroll
    for (int j = 0; j < KT; j++) {
        knx[j] = dup2(-2.0f * kb[m0 + j]);
        kny[j] = dup2(-2.0f * kb[MM + m0 + j]);
        knz[j] = dup2(-2.0f * kb[2 * MM + m0 + j]);
        mnl[j] = FLT_MAX;
        mnh[j] = FLT_MAX;
    }
    __syncthreads();

    // Main loop: pure compute against smem (broadcast LDS, conflict-free).
#pragma unroll 3
    for (int i = 0; i < TILE; i++) {
        ulonglong2 a = s_pts[2 * i];      // (x2, y2)
        ulonglong2 c = s_pts[2 * i + 1];  // (z2, pp)
#pragma unroll
        for (int j = 0; j < KT; j++) {
            u64 v = fma2(knx[j], a.x, fma2(kny[j], a.y, fma2(knz[j], c.x, c.y)));
            float lo, hi;
            unpack2(v, lo, hi);  // register-pair aliasing, no real MOVs
            mnl[j] = fminf(mnl[j], lo);
            mnh[j] = fminf(mnh[j], hi);
        }
    }

    // Coalesced store: 8 consecutive floats per thread (two STG.128).
    float* outp = g_partial + (size_t)chunk * NROWS + b * MM + m0;
    float4 o0, o1;
    o0.x = fminf(mnl[0], mnh[0]);
    o0.y = fminf(mnl[1], mnh[1]);
    o0.z = fminf(mnl[2], mnh[2]);
    o0.w = fminf(mnl[3], mnh[3]);
    o1.x = fminf(mnl[4], mnh[4]);
    o1.y = fminf(mnl[5], mnh[5]);
    o1.z = fminf(mnl[6], mnh[6]);
    o1.w = fminf(mnl[7], mnh[7]);
    ((float4*)outp)[0] = o0;
    ((float4*)outp)[1] = o1;

    // PDL: allow the dependent (final) kernel's blocks to launch; they park at
    // griddepcontrol.wait until this grid fully completes (stores visible).
    asm volatile("griddepcontrol.launch_dependents;");
}

// --- Kernel 2 (PDL secondary): 64 blocks = 64 rows x 4 chunk-quarters.
// Everything independent of g_partial runs BEFORE griddepcontrol.wait so it
// overlaps with min_kernel's tail.
__global__ void __launch_bounds__(256)
final_kernel(const float* __restrict__ kpt, float* __restrict__ out) {
    const int t    = threadIdx.x;
    const int row  = t & 63;          // row within this block's 64-row group
    const int q    = t >> 6;          // chunk quarter 0..3
    const int base = blockIdx.x * 64; // global row base

    // Prelude (overlapped with primary): keypoint |k|^2 for this thread's row.
    const int r0 = base + row;
    const int b0 = r0 >> 10, mm0 = r0 & (MM - 1);
    const float* kb0 = kpt + (size_t)b0 * 3 * MM;
    float kx = kb0[mm0], ky = kb0[MM + mm0], kz = kb0[2 * MM + mm0];
    float k2 = kx * kx + ky * ky + kz * kz;
    const float* p = g_partial + (size_t)q * CPQ * NROWS + r0;

    // Wait for min_kernel completion (g_partial now valid, L2-hot).
    asm volatile("griddepcontrol.wait;");

    // Quarter-min: 46 coalesced loads (lanes -> consecutive rows).
    float v = FLT_MAX;
#pragma unroll 8
    for (int c = 0; c < CPQ; c++)
        v = fminf(v, __ldcg(p + (size_t)c * NROWS));

    __shared__ float s_v[256];
    __shared__ float s_w[2];
    __shared__ unsigned s_last;
    s_v[t] = v;
    __syncthreads();

    // Combine quarters, finish rows, partial-sum (threads 0..63 = warps 0,1).
    if (t < 64) {
        float mv = fminf(fminf(s_v[t], s_v[t + 64]), fminf(s_v[t + 128], s_v[t + 192]));
        float d = sqrtf(fmaxf(mv + k2, 0.0f));  // k2 matches row: t==row for t<64
#pragma unroll
        for (int off = 16; off; off >>= 1) d += __shfl_xor_sync(0xffffffffu, d, off);
        if ((t & 31) == 0) s_w[t >> 5] = d;
    }
    __syncthreads();

    if (t == 0) {
        g_bsum[blockIdx.x] = s_w[0] + s_w[1];
        __threadfence();
        unsigned old = atomicAdd(&g_done, 1u);
        s_last = (old == FBLOCKS - 1) ? 1u : 0u;
    }
    __syncthreads();
    if (!s_last) return;

    // Last block: fold 64 block sums (fixed combine order -> deterministic).
    if (t < 64) {
        float s = __ldcg(g_bsum + t);
#pragma unroll
        for (int off = 16; off; off >>= 1) s += __shfl_xor_sync(0xffffffffu, s, off);
        if ((t & 31) == 0) s_w[t >> 5] = s;
    }
    __syncthreads();
    if (t == 0) {
        *out = (s_w[0] + s_w[1]) * (1.0f / (float)NROWS);
        g_done = 0;  // reset for next graph replay
    }
}

extern "C" void kernel_launch(void* const* d_in, const int* in_sizes, int n_in,
                              void* d_out, int out_size) {
    const float* keypoints = (const float*)d_in[0];  // [B,3,M]
    const float* pc        = (const float*)d_in[1];  // [B,3,N]
    float* out             = (float*)d_out;          // scalar

    (void)in_sizes; (void)n_in; (void)out_size;

    dim3 grid(NCHUNK, BB);
    min_kernel<<<grid, NTHREADS>>>(keypoints, pc);

    // Secondary launch with Programmatic Stream Serialization (PDL).
    cudaLaunchConfig_t cfg = {};
    cfg.gridDim  = dim3(FBLOCKS, 1, 1);
    cfg.blockDim = dim3(256, 1, 1);
    cfg.dynamicSmemBytes = 0;
    cfg.stream = (cudaStream_t)0;  // legacy default stream (the captured one)
    cudaLaunchAttribute attrs[1];
    attrs[0].id = cudaLaunchAttributeProgrammaticStreamSerialization;
    attrs[0].val.programmaticStreamSerializationAllowed = 1;
    cfg.attrs = attrs;
    cfg.numAttrs = 1;
    cudaLaunchKernelEx(&cfg, final_kernel, keypoints, out);
}

// round 14
// speedup vs baseline: 1.0767x; 1.0767x over previous
#include <cuda_runtime.h>
#include <float.h>

// Problem constants (fixed: B=4, M=1024, N=32768)
#define BB 4
#define MM 1024
#define NN 32768
#define NCHUNK 296             // 296*4 = 1184 blocks = exactly 8/SM (148 SMs), 1 wave at occ8
#define TILE 111               // ceil(32768/296) points per chunk; tail clamped at copy
#define KT 8                   // keypoints per thread (= 4 packed pairs)
#define KP 4                   // keypoint pairs per thread
#define NTHREADS 128           // 128 * 8 = 1024 = all keypoints per block
#define NROWS (BB * MM)        // 4096
#define FBLOCKS 64             // final blocks: 64 rows x 4 chunk-quarters each
#define CQ 4
#define CPQ (NCHUNK / CQ)      // 74 chunks per quarter

typedef unsigned long long u64;

// Scratch (no cudaMalloc allowed). Chunk-major: [chunk][b*MM+m]
__device__ float g_partial[NCHUNK * NROWS];
__device__ float g_bsum[FBLOCKS];
__device__ unsigned g_done;   // zero-init at load; last block resets -> replay-safe

// ---- packed f32x2 helpers (Blackwell FFMA2 path) ----
__device__ __forceinline__ u64 fma2(u64 a, u64 b, u64 c) {
    u64 d; asm("fma.rn.f32x2 %0, %1, %2, %3;" : "=l"(d) : "l"(a), "l"(b), "l"(c));
    return d;
}
__device__ __forceinline__ u64 mul2(u64 a, u64 b) {
    u64 d; asm("mul.rn.f32x2 %0, %1, %2;" : "=l"(d) : "l"(a), "l"(b));
    return d;
}
__device__ __forceinline__ u64 dup2(float x) {
    u64 d; asm("mov.b64 %0, {%1, %1};" : "=l"(d) : "f"(x));
    return d;
}
__device__ __forceinline__ void unpack2(u64 v, float& lo, float& hi) {
    asm("mov.b64 {%0, %1}, %2;" : "=f"(lo), "=f"(hi) : "l"(v));
}

// --- Kernel 1: per (chunk, b) block: min over chunk's points for all 1024 keypoints.
// v = |p|^2 - 2 k.p  (d2 = |k|^2 + min v applied in the final kernel).
// Packing: two KEYPOINTS per f32x2 lane; each point pre-duplicated in smem.
__global__ void __launch_bounds__(NTHREADS, 8)
min_kernel(const float* __restrict__ kpt, const float* __restrict__ pc) {
    const int chunk = blockIdx.x;
    const int b     = blockIdx.y;
    const int t     = threadIdx.x;
    const int m0    = t * KT;

    // smem per point i: s_pts[2i]={(x,x),(y,y)}, s_pts[2i+1]={(z,z),(pp,pp)}
    __shared__ ulonglong2 s_pts[2 * TILE];

    // Copy phase: stage duplicated point data + |p|^2 (computed once per point).
    if (t < TILE) {
        int q = min(chunk * TILE + t, NN - 1);  // tail clamp: dup point is a min no-op
        const float* pcb = pc + (size_t)b * 3 * NN;
        float x = pcb[q], y = pcb[NN + q], z = pcb[2 * NN + q];
        float pp = x * x + y * y + z * z;
        ulonglong2 a, c;
        a.x = dup2(x); a.y = dup2(y);
        c.x = dup2(z); c.y = dup2(pp);
        s_pts[2 * t]     = a;
        s_pts[2 * t + 1] = c;
    }

    // Per-thread keypoint PAIRS (consecutive m -> aligned LDG.64), scaled by -2.
    const float* kb = kpt + (size_t)b * 3 * MM;
    const u64* kxp = (const u64*)(kb + m0);
    const u64* kyp = (const u64*)(kb + MM + m0);
    const u64* kzp = (const u64*)(kb + 2 * MM + m0);
    const u64 neg2 = dup2(-2.0f);
    u64 knx[KP], kny[KP], knz[KP];
    float mn[KT];
#pragma unroll
    for (int u = 0; u < KP; u++) {
        knx[u] = mul2(neg2, kxp[u]);
        kny[u] = mul2(neg2, kyp[u]);
        knz[u] = mul2(neg2, kzp[u]);
    }
#pragma unroll
    for (int j = 0; j < KT; j++) mn[j] = FLT_MAX;
    __syncthreads();

    // Main loop: one point per iter, 4 keypoint-pairs -> 12 FFMA2 + 8 FMNMX.
#pragma unroll 3
    for (int i = 0; i < TILE; i++) {
        ulonglong2 a = s_pts[2 * i];      // (xd, yd)
        ulonglong2 c = s_pts[2 * i + 1];  // (zd, ppd)
#pragma unroll
        for (int u = 0; u < KP; u++) {
            u64 v = fma2(knx[u], a.x, fma2(kny[u], a.y, fma2(knz[u], c.x, c.y)));
            float lo, hi;
            unpack2(v, lo, hi);  // register-pair aliasing, no real MOVs
            mn[2 * u]     = fminf(mn[2 * u], lo);
            mn[2 * u + 1] = fminf(mn[2 * u + 1], hi);
        }
    }

    // Coalesced store: 8 consecutive floats per thread (two STG.128).
    float* outp = g_partial + (size_t)chunk * NROWS + b * MM + m0;
    float4 o0, o1;
    o0.x = mn[0]; o0.y = mn[1]; o0.z = mn[2]; o0.w = mn[3];
    o1.x = mn[4]; o1.y = mn[5]; o1.z = mn[6]; o1.w = mn[7];
    ((float4*)outp)[0] = o0;
    ((float4*)outp)[1] = o1;
}

// --- Kernel 2: 64 blocks; each block = 64 rows x 4 chunk-quarters (smem combine,
// no global atomics on the data path). Last block folds 64 block sums (fixed order).
__global__ void __launch_bounds__(256)
final_kernel(const float* __restrict__ kpt, float* __restrict__ out) {
    const int t    = threadIdx.x;
    const int row  = t & 63;          // row within this block's 64-row group
    const int q    = t >> 6;          // chunk quarter 0..3
    const int base = blockIdx.x * 64; // global row base

    // Quarter-min: 74 coalesced loads (lanes -> consecutive rows).
    float v = FLT_MAX;
    const float* p = g_partial + (size_t)q * CPQ * NROWS + base + row;
#pragma unroll 8
    for (int c = 0; c < CPQ; c++)
        v = fminf(v, __ldcg(p + (size_t)c * NROWS));

    __shared__ float s_v[256];
    __shared__ float s_w[2];
    __shared__ unsigned s_last;
    s_v[t] = v;
    __syncthreads();

    // Combine quarters, finish rows, partial-sum (threads 0..63 = warps 0,1).
    if (t < 64) {
        float mv = fminf(fminf(s_v[t], s_v[t + 64]), fminf(s_v[t + 128], s_v[t + 192]));
        int r = base + t;
        int b = r >> 10, m = r & (MM - 1);
        const float* kb = kpt + (size_t)b * 3 * MM;
        float x = kb[m], y = kb[MM + m], z = kb[2 * MM + m];
        float d = sqrtf(fmaxf(mv + (x * x + y * y + z * z), 0.0f));
#pragma unroll
        for (int off = 16; off; off >>= 1) d += __shfl_xor_sync(0xffffffffu, d, off);
        if ((t & 31) == 0) s_w[t >> 5] = d;
    }
    __syncthreads();

    if (t == 0) {
        g_bsum[blockIdx.x] = s_w[0] + s_w[1];
        __threadfence();
        unsigned old = atomicAdd(&g_done, 1u);
        s_last = (old == FBLOCKS - 1) ? 1u : 0u;
    }
    __syncthreads();
    if (!s_last) return;

    // Last block: fold 64 block sums in parallel (warps 0,1), fixed combine order.
    if (t < 64) {
        float s = __ldcg(g_bsum + t);
#pragma unroll
        for (int off = 16; off; off >>= 1) s += __shfl_xor_sync(0xffffffffu, s, off);
        if ((t & 31) == 0) s_w[t >> 5] = s;
    }
    __syncthreads();
    if (t == 0) {
        *out = (s_w[0] + s_w[1]) * (1.0f / (float)NROWS);
        g_done = 0;  // reset for next graph replay
    }
}

extern "C" void kernel_launch(void* const* d_in, const int* in_sizes, int n_in,
                              void* d_out, int out_size) {
    const float* keypoints = (const float*)d_in[0];  // [B,3,M]
    const float* pc        = (const float*)d_in[1];  // [B,3,N]
    float* out             = (float*)d_out;          // scalar

    (void)in_sizes; (void)n_in; (void)out_size;

    dim3 grid(NCHUNK, BB);
    min_kernel<<<grid, NTHREADS>>>(keypoints, pc);
    final_kernel<<<FBLOCKS, 256>>>(keypoints, out);
}

// round 15
// speedup vs baseline: 1.3553x; 1.2588x over previous
#include <cuda_runtime.h>
#include <float.h>

// Problem constants (fixed: B=4, M=1024, N=32768)
#define BB 4
#define MM 1024
#define NN 32768
#define NPAIRS (NN / 2)        // 16384 point-pairs per batch
#define NCHUNK 220             // 220*4 = 880 blocks < 888 = 148 SM * 6 -> 1 wave at occ6
#define TILE 75                // ceil(16384/220); tail clamped at copy time
#define KT 8                   // keypoints per thread
#define NTHREADS 128           // 128 * 8 = 1024 = all keypoints per block
#define NROWS (BB * MM)        // 4096
#define FBLOCKS 64             // final blocks: 64 rows x 4 chunk-quarters each
#define CQ 4
#define CPQ (NCHUNK / CQ)      // 55 chunks per quarter

typedef unsigned long long u64;

// Scratch (no cudaMalloc allowed). Chunk-major: [chunk][b*MM+m]
__device__ float g_partial[NCHUNK * NROWS];
__device__ float g_bsum[FBLOCKS];
__device__ unsigned g_done;   // zero-init at load; last block resets -> replay-safe

// ---- packed f32x2 helpers (Blackwell FFMA2 path) ----
__device__ __forceinline__ u64 fma2(u64 a, u64 b, u64 c) {
    u64 d; asm("fma.rn.f32x2 %0, %1, %2, %3;" : "=l"(d) : "l"(a), "l"(b), "l"(c));
    return d;
}
__device__ __forceinline__ u64 mul2(u64 a, u64 b) {
    u64 d; asm("mul.rn.f32x2 %0, %1, %2;" : "=l"(d) : "l"(a), "l"(b));
    return d;
}
__device__ __forceinline__ u64 dup2(float x) {
    u64 d; asm("mov.b64 %0, {%1, %1};" : "=l"(d) : "f"(x));
    return d;
}
__device__ __forceinline__ void unpack2(u64 v, float& lo, float& hi) {
    asm("mov.b64 {%0, %1}, %2;" : "=f"(lo), "=f"(hi) : "l"(v));
}

// --- Kernel 1 (R11 structure: two POINTS packed per f32x2 lane): per (chunk, b)
// block, min over chunk's point-pairs for all 1024 keypoints. v = |p|^2 - 2 k.p
__global__ void __launch_bounds__(NTHREADS, 6)
min_kernel(const float* __restrict__ kpt, const float* __restrict__ pc) {
    const int chunk = blockIdx.x;
    const int b     = blockIdx.y;
    const int t     = threadIdx.x;
    const int m0    = t * KT;

    // smem: per pair i: s_pts[2i]={x2,y2}, s_pts[2i+1]={z2,pp}  (two LDS.128 per iter)
    __shared__ ulonglong2 s_pts[2 * TILE];

    // Copy phase: stage this chunk's point-pairs + packed |p|^2 (computed once).
    if (t < TILE) {
        int q = min(chunk * TILE + t, NPAIRS - 1);  // tail clamp: dup pair is a min no-op
        const float* pcb = pc + (size_t)b * 3 * NN;
        u64 x2 = ((const u64*)pcb)[q];
        u64 y2 = ((const u64*)(pcb + NN))[q];
        u64 z2 = ((const u64*)(pcb + 2 * NN))[q];
        u64 pp = fma2(z2, z2, fma2(y2, y2, mul2(x2, x2)));  // (|p0|^2, |p1|^2)
        ulonglong2 a, c;
        a.x = x2; a.y = y2;
        c.x = z2; c.y = pp;
        s_pts[2 * t]     = a;
        s_pts[2 * t + 1] = c;
    }

    // Per-thread keypoints, scaled by -2, duplicated into both f32x2 halves (hoisted).
    const float* kb = kpt + (size_t)b * 3 * MM;
    u64 knx[KT], kny[KT], knz[KT];
    float mnl[KT], mnh[KT];
#pragma unroll
    for (int j = 0; j < KT; j++) {
        knx[j] = dup2(-2.0f * kb[m0 + j]);
        kny[j] = dup2(-2.0f * kb[MM + m0 + j]);
        knz[j] = dup2(-2.0f * kb[2 * MM + m0 + j]);
        mnl[j] = FLT_MAX;
        mnh[j] = FLT_MAX;
    }
    __syncthreads();

    // Main loop: pure compute against smem (broadcast LDS, conflict-free).
#pragma unroll 3
    for (int i = 0; i < TILE; i++) {
        ulonglong2 a = s_pts[2 * i];      // (x2, y2)
        ulonglong2 c = s_pts[2 * i + 1];  // (z2, pp)
#pragma unroll
        for (int j = 0; j < KT; j++) {
            u64 v = fma2(knx[j], a.x, fma2(kny[j], a.y, fma2(knz[j], c.x, c.y)));
            float lo, hi;
            unpack2(v, lo, hi);  // register-pair aliasing, no real MOVs
            mnl[j] = fminf(mnl[j], lo);
            mnh[j] = fminf(mnh[j], hi);
        }
    }

    // Coalesced store: 8 consecutive floats per thread (two STG.128).
    float* outp = g_partial + (size_t)chunk * NROWS + b * MM + m0;
    float4 o0, o1;
    o0.x = fminf(mnl[0], mnh[0]);
    o0.y = fminf(mnl[1], mnh[1]);
    o0.z = fminf(mnl[2], mnh[2]);
    o0.w = fminf(mnl[3], mnh[3]);
    o1.x = fminf(mnl[4], mnh[4]);
    o1.y = fminf(mnl[5], mnh[5]);
    o1.z = fminf(mnl[6], mnh[6]);
    o1.w = fminf(mnl[7], mnh[7]);
    ((float4*)outp)[0] = o0;
    ((float4*)outp)[1] = o1;
}

// --- Kernel 2: 64 blocks; each block = 64 rows x 4 chunk-quarters (smem combine,
// no global atomics on the data path). Last block folds 64 block sums (fixed order).
__global__ void __launch_bounds__(256)
final_kernel(const float* __restrict__ kpt, float* __restrict__ out) {
    const int t    = threadIdx.x;
    const int row  = t & 63;          // row within this block's 64-row group
    const int q    = t >> 6;          // chunk quarter 0..3
    const int base = blockIdx.x * 64; // global row base

    // Quarter-min: 55 coalesced loads (lanes -> consecutive rows).
    float v = FLT_MAX;
    const float* p = g_partial + (size_t)q * CPQ * NROWS + base + row;
#pragma unroll 8
    for (int c = 0; c < CPQ; c++)
        v = fminf(v, __ldcg(p + (size_t)c * NROWS));

    __shared__ float s_v[256];
    __shared__ float s_w[2];
    __shared__ unsigned s_last;
    s_v[t] = v;
    __syncthreads();

    // Combine quarters, finish rows, partial-sum (threads 0..63 = warps 0,1).
    if (t < 64) {
        float mv = fminf(fminf(s_v[t], s_v[t + 64]), fminf(s_v[t + 128], s_v[t + 192]));
        int r = base + t;
        int b = r >> 10, m = r & (MM - 1);
        const float* kb = kpt + (size_t)b * 3 * MM;
        float x = kb[m], y = kb[MM + m], z = kb[2 * MM + m];
        float d = sqrtf(fmaxf(mv + (x * x + y * y + z * z), 0.0f));
#pragma unroll
        for (int off = 16; off; off >>= 1) d += __shfl_xor_sync(0xffffffffu, d, off);
        if ((t & 31) == 0) s_w[t >> 5] = d;
    }
    __syncthreads();

    if (t == 0) {
        g_bsum[blockIdx.x] = s_w[0] + s_w[1];
        __threadfence();
        unsigned old = atomicAdd(&g_done, 1u);
        s_last = (old == FBLOCKS - 1) ? 1u : 0u;
    }
    __syncthreads();
    if (!s_last) return;

    // Last block: fold 64 block sums in parallel (warps 0,1), fixed combine order.
    if (t < 64) {
        float s = __ldcg(g_bsum + t);
#pragma unroll
        for (int off = 16; off; off >>= 1) s += __shfl_xor_sync(0xffffffffu, s, off);
        if ((t & 31) == 0) s_w[t >> 5] = s;
    }
    __syncthreads();
    if (t == 0) {
        *out = (s_w[0] + s_w[1]) * (1.0f / (float)NROWS);
        g_done = 0;  // reset for next graph replay
    }
}

extern "C" void kernel_launch(void* const* d_in, const int* in_sizes, int n_in,
                              void* d_out, int out_size) {
    const float* keypoints = (const float*)d_in[0];  // [B,3,M]
    const float* pc        = (const float*)d_in[1];  // [B,3,N]
    float* out             = (float*)d_out;          // scalar

    (void)in_sizes; (void)n_in; (void)out_size;

    dim3 grid(NCHUNK, BB);
    min_kernel<<<grid, NTHREADS>>>(keypoints, pc);
    final_kernel<<<FBLOCKS, 256>>>(keypoints, out);
}

// round 17
// speedup vs baseline: 1.3718x; 1.0122x over previous
#include <cuda_runtime.h>
#include <float.h>

// Problem constants (fixed: B=4, M=1024, N=32768)
#define BB 4
#define MM 1024
#define NN 32768
#define NPAIRS (NN / 2)        // 16384 point-pairs per batch
#define NCHUNK 148             // 148*4 = 592 blocks = exactly 4/SM -> 32 warps/SM at 256 thr
#define TILE 111               // ceil(16384/148); tail clamped at copy time
#define KT 4                   // keypoints per thread
#define NTHREADS 256           // 256 * 4 = 1024 = all keypoints per block
#define NROWS (BB * MM)        // 4096
#define FBLOCKS 64             // final blocks: 64 rows x 4 chunk-quarters each
#define CQ 4
#define CPQ (NCHUNK / CQ)      // 37 chunks per quarter

typedef unsigned long long u64;

// Scratch (no cudaMalloc allowed). Chunk-major: [chunk][b*MM+m]
__device__ float g_partial[NCHUNK * NROWS];
__device__ float g_bsum[FBLOCKS];
__device__ unsigned g_done;   // zero-init at load; last block resets -> replay-safe

// ---- packed f32x2 helpers (Blackwell FFMA2 path) ----
__device__ __forceinline__ u64 fma2(u64 a, u64 b, u64 c) {
    u64 d; asm("fma.rn.f32x2 %0, %1, %2, %3;" : "=l"(d) : "l"(a), "l"(b), "l"(c));
    return d;
}
__device__ __forceinline__ u64 mul2(u64 a, u64 b) {
    u64 d; asm("mul.rn.f32x2 %0, %1, %2;" : "=l"(d) : "l"(a), "l"(b));
    return d;
}
__device__ __forceinline__ u64 dup2(float x) {
    u64 d; asm("mov.b64 %0, {%1, %1};" : "=l"(d) : "f"(x));
    return d;
}
__device__ __forceinline__ void unpack2(u64 v, float& lo, float& hi) {
    asm("mov.b64 {%0, %1}, %2;" : "=f"(lo), "=f"(hi) : "l"(v));
}

// --- Kernel 1: per (chunk, b) block: min over chunk's point-pairs for all 1024
// keypoints. v = |p|^2 - 2 k.p  (d2 = |k|^2 + min v applied in final kernel).
// R11 inner loop (2 points packed per f32x2 lane); 256 threads, KT=4, 32 warps/SM.
__global__ void __launch_bounds__(NTHREADS, 4)
min_kernel(const float* __restrict__ kpt, const float* __restrict__ pc) {
    const int chunk = blockIdx.x;
    const int b     = blockIdx.y;
    const int t     = threadIdx.x;
    const int m0    = t * KT;

    // smem: per pair i: s_pts[2i]={x2,y2}, s_pts[2i+1]={z2,pp}  (two LDS.128 per iter)
    __shared__ ulonglong2 s_pts[2 * TILE];

    // Copy phase: stage this chunk's point-pairs + packed |p|^2 (computed once).
    if (t < TILE) {
        int q = min(chunk * TILE + t, NPAIRS - 1);  // tail clamp: dup pair is a min no-op
        const float* pcb = pc + (size_t)b * 3 * NN;
        u64 x2 = ((const u64*)pcb)[q];
        u64 y2 = ((const u64*)(pcb + NN))[q];
        u64 z2 = ((const u64*)(pcb + 2 * NN))[q];
        u64 pp = fma2(z2, z2, fma2(y2, y2, mul2(x2, x2)));  // (|p0|^2, |p1|^2)
        ulonglong2 a, c;
        a.x = x2; a.y = y2;
        c.x = z2; c.y = pp;
        s_pts[2 * t]     = a;
        s_pts[2 * t + 1] = c;
    }

    // Per-thread keypoints, scaled by -2, duplicated into both f32x2 halves (hoisted).
    const float* kb = kpt + (size_t)b * 3 * MM;
    u64 knx[KT], kny[KT], knz[KT];
    float mnl[KT], mnh[KT];
#pragma unroll
    for (int j = 0; j < KT; j++) {
        knx[j] = dup2(-2.0f * kb[m0 + j]);
        kny[j] = dup2(-2.0f * kb[MM + m0 + j]);
        knz[j] = dup2(-2.0f * kb[2 * MM + m0 + j]);
        mnl[j] = FLT_MAX;
        mnh[j] = FLT_MAX;
    }
    __syncthreads();

    // Main loop: pure compute against smem (broadcast LDS, conflict-free).
#pragma unroll 3
    for (int i = 0; i < TILE; i++) {
        ulonglong2 a = s_pts[2 * i];      // (x2, y2)
        ulonglong2 c = s_pts[2 * i + 1];  // (z2, pp)
#pragma unroll
        for (int j = 0; j < KT; j++) {
            u64 v = fma2(knx[j], a.x, fma2(kny[j], a.y, fma2(knz[j], c.x, c.y)));
            float lo, hi;
            unpack2(v, lo, hi);  // register-pair aliasing, no real MOVs
            mnl[j] = fminf(mnl[j], lo);
            mnh[j] = fminf(mnh[j], hi);
        }
    }

    // Coalesced store: 4 consecutive floats per thread (one STG.128).
    float* outp = g_partial + (size_t)chunk * NROWS + b * MM + m0;
    float4 o;
    o.x = fminf(mnl[0], mnh[0]);
    o.y = fminf(mnl[1], mnh[1]);
    o.z = fminf(mnl[2], mnh[2]);
    o.w = fminf(mnl[3], mnh[3]);
    *(float4*)outp = o;
}

// --- Kernel 2: 64 blocks; each block = 64 rows x 4 chunk-quarters (smem combine,
// no global atomics on the data path). Last block folds 64 block sums (fixed order).
__global__ void __launch_bounds__(256)
final_kernel(const float* __restrict__ kpt, float* __restrict__ out) {
    const int t    = threadIdx.x;
    const int row  = t & 63;          // row within this block's 64-row group
    const int q    = t >> 6;          // chunk quarter 0..3
    const int base = blockIdx.x * 64; // global row base

    // Quarter-min: 37 coalesced loads (lanes -> consecutive rows).
    float v = FLT_MAX;
    const float* p = g_partial + (size_t)q * CPQ * NROWS + base + row;
#pragma unroll 8
    for (int c = 0; c < CPQ; c++)
        v = fminf(v, __ldcg(p + (size_t)c * NROWS));

    __shared__ float s_v[256];
    __shared__ float s_w[2];
    __shared__ unsigned s_last;
    s_v[t] = v;
    __syncthreads();

    // Combine quarters, finish rows, partial-sum (threads 0..63 = warps 0,1).
    if (t < 64) {
        float mv = fminf(fminf(s_v[t], s_v[t + 64]), fminf(s_v[t + 128], s_v[t + 192]));
        int r = base + t;
        int b = r >> 10, m = r & (MM - 1);
        const float* kb = kpt + (size_t)b * 3 * MM;
        float x = kb[m], y = kb[MM + m], z = kb[2 * MM + m];
        float d = sqrtf(fmaxf(mv + (x * x + y * y + z * z), 0.0f));
#pragma unroll
        for (int off = 16; off; off >>= 1) d += __shfl_xor_sync(0xffffffffu, d, off);
        if ((t & 31) == 0) s_w[t >> 5] = d;
    }
    __syncthreads();

    if (t == 0) {
        g_bsum[blockIdx.x] = s_w[0] + s_w[1];
        __threadfence();
        unsigned old = atomicAdd(&g_done, 1u);
        s_last = (old == FBLOCKS - 1) ? 1u : 0u;
    }
    __syncthreads();
    if (!s_last) return;

    // Last block: fold 64 block sums in parallel (warps 0,1), fixed combine order.
    if (t < 64) {
        float s = __ldcg(g_bsum + t);
#pragma unroll
        for (int off = 16; off; off >>= 1) s += __shfl_xor_sync(0xffffffffu, s, off);
        if ((t & 31) == 0) s_w[t >> 5] = s;
    }
    __syncthreads();
    if (t == 0) {
        *out = (s_w[0] + s_w[1]) * (1.0f / (float)NROWS);
        g_done = 0;  // reset for next graph replay
    }
}

extern "C" void kernel_launch(void* const* d_in, const int* in_sizes, int n_in,
                              void* d_out, int out_size) {
    const float* keypoints = (const float*)d_in[0];  // [B,3,M]
    const float* pc        = (const float*)d_in[1];  // [B,3,N]
    float* out             = (float*)d_out;          // scalar

    (void)in_sizes; (void)n_in; (void)out_size;

    dim3 grid(NCHUNK, BB);
    min_kernel<<<grid, NTHREADS>>>(keypoints, pc);
    final_kernel<<<FBLOCKS, 256>>>(keypoints, out);
}